// round 15
// baseline (speedup 1.0000x reference)
#include <cuda_runtime.h>
#include <cuda_fp16.h>
#include <math.h>
#include <cstdint>

// Problem constants
#define D_DIM 2048
#define S_LEN 2048
#define B_SZ  4
#define NHEAD 16
#define HD    128
#define MROWS (B_SZ * S_LEN)   // 8192
#define NQKV  (3 * D_DIM)      // 6144

// ---------------------------------------------------------------------------
// Scratch (device globals: allocation-guard-safe)
// ---------------------------------------------------------------------------
__device__ __half g_xh[(size_t)MROWS * D_DIM];
__device__ __half g_wqkvh[(size_t)NQKV * D_DIM];     // [wq; wk; wv] rows
__device__ __half g_woh[(size_t)D_DIM * D_DIM];
__device__ __half g_QKVh[(size_t)MROWS * NQKV];      // Q|K|V per row
__device__ __half g_Oh[(size_t)MROWS * D_DIM];

// ---------------------------------------------------------------------------
// Helpers
// ---------------------------------------------------------------------------
__device__ __forceinline__ uint32_t smem_u32(const void* p) {
    uint32_t a;
    asm("{ .reg .u64 t; cvta.to.shared.u64 t, %1; cvt.u32.u64 %0, t; }"
        : "=r"(a) : "l"(p));
    return a;
}
__device__ __forceinline__ void cp_async16(uint32_t saddr, const void* gaddr) {
    asm volatile("cp.async.cg.shared.global [%0], [%1], 16;"
                 :: "r"(saddr), "l"(gaddr) : "memory");
}
__device__ __forceinline__ void cp_commit() {
    asm volatile("cp.async.commit_group;" ::: "memory");
}
template <int N> __device__ __forceinline__ void cp_wait() {
    asm volatile("cp.async.wait_group %0;" :: "n"(N) : "memory");
}
__device__ __forceinline__ uint32_t pack_h2(float lo, float hi) {
    uint32_t r;
    asm("cvt.rn.f16x2.f32 %0, %1, %2;" : "=r"(r) : "f"(hi), "f"(lo));
    return r;
}
__device__ __forceinline__ float ex2f(float x) {
    float r;
    asm("ex2.approx.f32 %0, %1;" : "=f"(r) : "f"(x));
    return r;
}
__device__ __forceinline__ uint32_t ex2h2(uint32_t x) {
    uint32_t r;
    asm("ex2.approx.f16x2 %0, %1;" : "=r"(r) : "r"(x));
    return r;
}
__device__ __forceinline__ void mma_f16(float* d, const uint32_t* a, const uint32_t* b) {
    asm volatile(
        "mma.sync.aligned.m16n8k16.row.col.f32.f16.f16.f32 "
        "{%0,%1,%2,%3}, {%4,%5,%6,%7}, {%8,%9}, {%0,%1,%2,%3};"
        : "+f"(d[0]), "+f"(d[1]), "+f"(d[2]), "+f"(d[3])
        : "r"(a[0]), "r"(a[1]), "r"(a[2]), "r"(a[3]), "r"(b[0]), "r"(b[1]));
}
__device__ __forceinline__ void ldmx4(uint32_t& r0, uint32_t& r1,
                                      uint32_t& r2, uint32_t& r3, uint32_t addr) {
    asm volatile("ldmatrix.sync.aligned.m8n8.x4.shared.b16 {%0,%1,%2,%3}, [%4];"
                 : "=r"(r0), "=r"(r1), "=r"(r2), "=r"(r3) : "r"(addr));
}
__device__ __forceinline__ void ldmx4t(uint32_t& r0, uint32_t& r1,
                                       uint32_t& r2, uint32_t& r3, uint32_t addr) {
    asm volatile("ldmatrix.sync.aligned.m8n8.x4.trans.shared.b16 {%0,%1,%2,%3}, [%4];"
                 : "=r"(r0), "=r"(r1), "=r"(r2), "=r"(r3) : "r"(addr));
}

// ---------------------------------------------------------------------------
// fp32 -> fp16 conversion (RN)
// ---------------------------------------------------------------------------
__global__ void h_cvt_kernel(const float4* __restrict__ in,
                             uint2* __restrict__ out, int n4) {
    int i = blockIdx.x * blockDim.x + threadIdx.x;
    if (i < n4) {
        float4 v = in[i];
        out[i] = make_uint2(pack_h2(v.x, v.y), pack_h2(v.z, v.w));
    }
}
// wq/wk/wv -> contiguous wqkvh regions; wo -> woh. One launch.
__global__ void h_cvt4_kernel(const float4* __restrict__ s0,
                              const float4* __restrict__ s1,
                              const float4* __restrict__ s2,
                              const float4* __restrict__ s3,
                              uint2* __restrict__ out012,
                              uint2* __restrict__ out3, int n4each) {
    const int y = blockIdx.y;
    const float4* src = (y == 0) ? s0 : (y == 1) ? s1 : (y == 2) ? s2 : s3;
    int i = blockIdx.x * blockDim.x + threadIdx.x;
    if (i < n4each) {
        float4 v = src[i];
        uint2 r = make_uint2(pack_h2(v.x, v.y), pack_h2(v.z, v.w));
        if (y < 3) out012[(size_t)y * n4each + i] = r;
        else       out3[i] = r;
    }
}

// ---------------------------------------------------------------------------
// fp16 HMMA GEMM: C[M,N] = A[M,K] * B[N,K]^T, fp32 accumulate.
// 128x128 CTA, 256 threads, 8 warps (4m x 2n), warp tile 32x64, BK=64,
// 3-stage cp.async (2 CTAs/SM), incremental global pointers,
// batched ldmatrix per k-step, XOR-carrier addressing. (R10 config — proven)
// ---------------------------------------------------------------------------
#define BKH 64
#define GTILE_BYTES (128 * BKH * 2)        // 16384
#define GSTAGE_BYTES (2 * GTILE_BYTES)     // 32768
#define GEMM_SMEM_BYTES (3 * GSTAGE_BYTES) // 98304

template <bool HALF_OUT>
__global__ __launch_bounds__(256, 2)
void gemm_f16_kernel(const __half* __restrict__ A,
                     const __half* __restrict__ B,
                     void* __restrict__ Cv,
                     int M, int N, int K)
{
    extern __shared__ char smem[];
    const uint32_t sbase = smem_u32(smem);
    const int tid  = threadIdx.x;
    const int wid  = tid >> 5;
    const int lane = tid & 31;
    const int wm   = wid >> 1;
    const int wn   = wid & 1;
    const int g    = lane >> 2;
    const int t    = lane & 3;
    const int bm0 = blockIdx.y * 128;
    const int bn0 = blockIdx.x * 128;

    const int lr = tid >> 3;
    const int lc = tid & 7;
    const __half* aptr = A + (size_t)(bm0 + lr) * K + lc * 8;
    const __half* bptr = B + (size_t)(bn0 + lr) * K + lc * 8;
    const uint32_t sAoff = (uint32_t)(lr * 128 + ((lc ^ (lr & 7)) << 4));
    const size_t gstep = (size_t)32 * K;

    const int lrow = lane & 15;
    const uint32_t chx = (uint32_t)(lane >> 4) << 4;
    const uint32_t relA0 = (uint32_t)((wm * 32 + lrow) * 128 + ((lrow & 7) << 4));
    const uint32_t relA1 = relA0 + 16 * 128;
    const uint32_t relB0 = (uint32_t)((wn * 64 + lrow) * 128 + ((lrow & 7) << 4));

    float acc[2][8][4];
    #pragma unroll
    for (int mt = 0; mt < 2; ++mt)
        #pragma unroll
        for (int nt = 0; nt < 8; ++nt)
            #pragma unroll
            for (int i = 0; i < 4; ++i) acc[mt][nt][i] = 0.0f;

    const int KT = K / BKH;

    #pragma unroll
    for (int st = 0; st < 2; ++st) {
        const uint32_t sb = sbase + (uint32_t)st * GSTAGE_BYTES + sAoff;
        #pragma unroll
        for (int i = 0; i < 4; ++i)
            cp_async16(sb + (uint32_t)(i * 4096), aptr + (size_t)i * gstep);
        #pragma unroll
        for (int i = 0; i < 4; ++i)
            cp_async16(sb + GTILE_BYTES + (uint32_t)(i * 4096), bptr + (size_t)i * gstep);
        cp_commit();
        aptr += BKH; bptr += BKH;
    }

    for (int kt = 0; kt < KT; ++kt) {
        const int s = kt % 3;
        if (kt == KT - 1) cp_wait<0>(); else cp_wait<1>();
        __syncthreads();

        if (kt + 2 < KT) {
            const uint32_t sb = sbase + (uint32_t)((kt + 2) % 3) * GSTAGE_BYTES + sAoff;
            #pragma unroll
            for (int i = 0; i < 4; ++i)
                cp_async16(sb + (uint32_t)(i * 4096), aptr + (size_t)i * gstep);
            #pragma unroll
            for (int i = 0; i < 4; ++i)
                cp_async16(sb + GTILE_BYTES + (uint32_t)(i * 4096), bptr + (size_t)i * gstep);
            cp_commit();
            aptr += BKH; bptr += BKH;
        }

        const uint32_t abase = sbase + (uint32_t)s * GSTAGE_BYTES;
        const uint32_t pA0 = (abase + relA0) ^ chx;
        const uint32_t pA1 = (abase + relA1) ^ chx;
        const uint32_t pB  = (abase + GTILE_BYTES + relB0) ^ chx;

        #pragma unroll
        for (int ks = 0; ks < 4; ++ks) {
            const uint32_t kx = (uint32_t)(ks * 32);
            uint32_t a0[4], a1[4], bf[4][4];
            ldmx4(a0[0], a0[1], a0[2], a0[3], pA0 ^ kx);
            ldmx4(a1[0], a1[1], a1[2], a1[3], pA1 ^ kx);
            #pragma unroll
            for (int nb = 0; nb < 4; ++nb)
                ldmx4(bf[nb][0], bf[nb][1], bf[nb][2], bf[nb][3],
                      (pB + (uint32_t)(nb * 2048)) ^ kx);
            #pragma unroll
            for (int nb = 0; nb < 4; ++nb) {
                uint32_t be[2] = {bf[nb][0], bf[nb][2]};
                uint32_t bo[2] = {bf[nb][1], bf[nb][3]};
                mma_f16(acc[0][2 * nb],     a0, be);
                mma_f16(acc[0][2 * nb + 1], a0, bo);
                mma_f16(acc[1][2 * nb],     a1, be);
                mma_f16(acc[1][2 * nb + 1], a1, bo);
            }
        }
    }

    #pragma unroll
    for (int mt = 0; mt < 2; ++mt) {
        int row = bm0 + wm * 32 + mt * 16 + g;
        #pragma unroll
        for (int nt = 0; nt < 8; ++nt) {
            int col = bn0 + wn * 64 + nt * 8 + t * 2;
            if (HALF_OUT) {
                __half* C = (__half*)Cv;
                *(uint32_t*)(C + (size_t)row * N + col) =
                    pack_h2(acc[mt][nt][0], acc[mt][nt][1]);
                *(uint32_t*)(C + (size_t)(row + 8) * N + col) =
                    pack_h2(acc[mt][nt][2], acc[mt][nt][3]);
            } else {
                float* C = (float*)Cv;
                *(float2*)(C + (size_t)row * N + col) =
                    make_float2(acc[mt][nt][0], acc[mt][nt][1]);
                *(float2*)(C + (size_t)(row + 8) * N + col) =
                    make_float2(acc[mt][nt][2], acc[mt][nt][3]);
            }
        }
    }
}

// ---------------------------------------------------------------------------
// fp16 tensor-core causal flash attention.
// Softmax: f16x2 approx exp (half the MUFU ops), row sums via tensor-core
// MMA against a ones-fragment (no FADD/shuffle reduction).
// ---------------------------------------------------------------------------
#define QT  128
#define KVT 64
#define ATT_Q_BYTES  (QT * 256)                   // 32768
#define ATT_K_BYTES  (KVT * 256)                  // 16384
#define ATT_K_OFF    ATT_Q_BYTES
#define ATT_V_OFF    (ATT_K_OFF + 2 * ATT_K_BYTES)
#define ATT_SMEM_BYTES (ATT_V_OFF + 2 * ATT_K_BYTES)   // 98304

// scale * log2(e) = (1/sqrt(128)) * 1.4426950408889634
#define ATT_C1 0.12751744518362732f

__device__ __forceinline__ void attn_load_kv(uint32_t sbase, int stage,
                                             const __half* __restrict__ KV,
                                             size_t gbase, int k0, int tid) {
    #pragma unroll
    for (int i = 0; i < 4; ++i) {
        int idx = tid + i * 256;
        int r = idx >> 4;
        int c = idx & 15;
        uint32_t dst = sbase + ATT_K_OFF + (uint32_t)stage * ATT_K_BYTES
                     + (uint32_t)(r * 256 + ((c ^ (r & 7)) << 4));
        cp_async16(dst, KV + gbase + 2048 + (size_t)(k0 + r) * NQKV + c * 8);
    }
    #pragma unroll
    for (int i = 0; i < 4; ++i) {
        int idx = tid + i * 256;
        int r = idx >> 4;
        int c = idx & 15;
        uint32_t dst = sbase + ATT_V_OFF + (uint32_t)stage * ATT_K_BYTES
                     + (uint32_t)(r * 256 + ((c ^ (r & 7)) << 4));
        cp_async16(dst, KV + gbase + 4096 + (size_t)(k0 + r) * NQKV + c * 8);
    }
    cp_commit();
}

__global__ __launch_bounds__(256, 2)
void attn_f16_kernel(const __half* __restrict__ QKV,
                     __half* __restrict__ O)
{
    extern __shared__ char smc[];
    const uint32_t sbase = smem_u32(smc);

    const int tid  = threadIdx.x;
    const int wid  = tid >> 5;
    const int lane = tid & 31;
    const int g    = lane >> 2;
    const int t    = lane & 3;
    const int q0 = (gridDim.x - 1 - blockIdx.x) * QT;
    const int h  = blockIdx.y;
    const int b  = blockIdx.z;
    const size_t gbase = ((size_t)b * S_LEN) * NQKV + (size_t)h * HD;

    const int lrow = lane & 15;
    const uint32_t chx = (uint32_t)(lane >> 4) << 4;
    const int r0 = wid * 16;

    const uint32_t relQ = (uint32_t)((r0 + lrow) * 256 + ((lrow & 7) << 4));
    const uint32_t relK = (uint32_t)(lrow * 256 + ((lrow & 7) << 4));
    const uint32_t pQ = (sbase + relQ) ^ chx;

    // Q tile: 128 rows x 128 halves, swizzled.
    #pragma unroll
    for (int i = 0; i < 8; ++i) {
        int idx = tid + i * 256;
        int r = idx >> 4;
        int c = idx & 15;
        uint32_t dst = sbase + (uint32_t)(r * 256 + ((c ^ (r & 7)) << 4));
        cp_async16(dst, QKV + gbase + (size_t)(q0 + r) * NQKV + c * 8);
    }
    attn_load_kv(sbase, 0, QKV, gbase, 0, tid);

    float o[16][4];
    #pragma unroll
    for (int j = 0; j < 16; ++j)
        #pragma unroll
        for (int i = 0; i < 4; ++i) o[j][i] = 0.0f;
    float m2[2] = {-INFINITY, -INFINITY};
    float l2[2] = {0.0f, 0.0f};

    const int ntiles = q0 / KVT + 2;

    for (int tt = 0; tt < ntiles; ++tt) {
        const int s = tt & 1;
        cp_wait<0>();
        __syncthreads();
        if (tt + 1 < ntiles)
            attn_load_kv(sbase, s ^ 1, QKV, gbase, (tt + 1) * KVT, tid);

        const int kk0 = tt * KVT;
        if (kk0 <= q0 + r0 + 15) {
            const uint32_t kb = sbase + ATT_K_OFF + (uint32_t)s * ATT_K_BYTES;
            const uint32_t vb = sbase + ATT_V_OFF + (uint32_t)s * ATT_K_BYTES;
            const uint32_t pK = (kb + relK) ^ chx;
            const uint32_t pV = (vb + relK) ^ chx;

            // ---- QK^T: 16x64 scores per warp ----
            float sc[8][4];
            #pragma unroll
            for (int j = 0; j < 8; ++j)
                #pragma unroll
                for (int i = 0; i < 4; ++i) sc[j][i] = 0.0f;

            #pragma unroll
            for (int ks = 0; ks < 8; ++ks) {
                const uint32_t kx = (uint32_t)(ks * 32);
                uint32_t a[4];
                ldmx4(a[0], a[1], a[2], a[3], pQ ^ kx);
                #pragma unroll
                for (int nb = 0; nb < 4; ++nb) {
                    uint32_t bf[4];
                    ldmx4(bf[0], bf[1], bf[2], bf[3],
                          (pK + (uint32_t)(nb * 4096)) ^ kx);
                    uint32_t be[2] = {bf[0], bf[2]};
                    uint32_t bo[2] = {bf[1], bf[3]};
                    mma_f16(sc[2 * nb],     a, be);
                    mma_f16(sc[2 * nb + 1], a, bo);
                }
            }

            // ---- causal mask (diagonal tiles only) ----
            if (kk0 + KVT - 1 > q0 + r0) {
                #pragma unroll
                for (int j = 0; j < 8; ++j) {
                    int colb = kk0 + j * 8 + 2 * t;
                    int rowa = q0 + r0 + g;
                    if (colb     > rowa)     sc[j][0] = -INFINITY;
                    if (colb + 1 > rowa)     sc[j][1] = -INFINITY;
                    if (colb     > rowa + 8) sc[j][2] = -INFINITY;
                    if (colb + 1 > rowa + 8) sc[j][3] = -INFINITY;
                }
            }

            // ---- online max + alpha (rows g and g+8) ----
            float alpha2[2], base2[2];
            #pragma unroll
            for (int half = 0; half < 2; ++half) {
                const int i0 = half * 2;
                float rmax = -INFINITY;
                #pragma unroll
                for (int j = 0; j < 8; ++j)
                    rmax = fmaxf(rmax, fmaxf(sc[j][i0], sc[j][i0 + 1]));
                rmax = fmaxf(rmax, __shfl_xor_sync(0xffffffffu, rmax, 1));
                rmax = fmaxf(rmax, __shfl_xor_sync(0xffffffffu, rmax, 2));
                float mold = m2[half];
                float mnew = fmaxf(mold, rmax);
                alpha2[half] = ex2f((mold - mnew) * ATT_C1);
                m2[half] = mnew;
                base2[half] = mnew * ATT_C1;
            }
            #pragma unroll
            for (int j = 0; j < 16; ++j) {
                o[j][0] *= alpha2[0]; o[j][1] *= alpha2[0];
                o[j][2] *= alpha2[1]; o[j][3] *= alpha2[1];
            }

            // ---- exp via f16x2: P fragments built directly ----
            uint32_t ph[8][2];
            #pragma unroll
            for (int j = 0; j < 8; ++j) {
                ph[j][0] = ex2h2(pack_h2(fmaf(sc[j][0], ATT_C1, -base2[0]),
                                         fmaf(sc[j][1], ATT_C1, -base2[0])));
                ph[j][1] = ex2h2(pack_h2(fmaf(sc[j][2], ATT_C1, -base2[1]),
                                         fmaf(sc[j][3], ATT_C1, -base2[1])));
            }

            // ---- PV + row-sum MMAs ----
            float racc[4] = {0.0f, 0.0f, 0.0f, 0.0f};
            const uint32_t ones2[2] = {0x3C003C00u, 0x3C003C00u};
            #pragma unroll
            for (int kk = 0; kk < 4; ++kk) {
                uint32_t a[4] = {ph[2 * kk][0], ph[2 * kk][1],
                                 ph[2 * kk + 1][0], ph[2 * kk + 1][1]};
                mma_f16(racc, a, ones2);       // row sums (all cols identical)
                const uint32_t pVk = pV + (uint32_t)(kk * 4096);
                #pragma unroll
                for (int pair = 0; pair < 8; ++pair) {
                    uint32_t v0, v1, v2, v3;
                    ldmx4t(v0, v1, v2, v3, pVk ^ (uint32_t)(pair * 32));
                    uint32_t b0[2] = {v0, v1};
                    uint32_t b1[2] = {v2, v3};
                    mma_f16(o[pair * 2],     a, b0);
                    mma_f16(o[pair * 2 + 1], a, b1);
                }
            }
            l2[0] = l2[0] * alpha2[0] + racc[0];
            l2[1] = l2[1] * alpha2[1] + racc[2];
        }
    }

    // ---- epilogue: normalize, store fp16 O [MROWS x D_DIM] ----
    const float inv0 = 1.0f / l2[0];
    const float inv1 = 1.0f / l2[1];
    const int rowa = q0 + r0 + g;
    const size_t obase = ((size_t)b * S_LEN) * D_DIM + (size_t)h * HD;
    #pragma unroll
    for (int j = 0; j < 16; ++j) {
        int col = j * 8 + 2 * t;
        *(uint32_t*)(O + obase + (size_t)rowa * D_DIM + col) =
            pack_h2(o[j][0] * inv0, o[j][1] * inv0);
        *(uint32_t*)(O + obase + (size_t)(rowa + 8) * D_DIM + col) =
            pack_h2(o[j][2] * inv1, o[j][3] * inv1);
    }
}

// ---------------------------------------------------------------------------
// Launch
// ---------------------------------------------------------------------------
extern "C" void kernel_launch(void* const* d_in, const int* in_sizes, int n_in,
                              void* d_out, int out_size)
{
    const float* x  = (const float*)d_in[0];
    const float* wq = (const float*)d_in[1];
    const float* wk = (const float*)d_in[2];
    const float* wv = (const float*)d_in[3];
    const float* wo = (const float*)d_in[4];
    float* out = (float*)d_out;

    __half *xh, *wqkvh, *woh, *qkvh, *oh;
    cudaGetSymbolAddress((void**)&xh,    g_xh);
    cudaGetSymbolAddress((void**)&wqkvh, g_wqkvh);
    cudaGetSymbolAddress((void**)&woh,   g_woh);
    cudaGetSymbolAddress((void**)&qkvh,  g_QKVh);
    cudaGetSymbolAddress((void**)&oh,    g_Oh);

    static bool attr_set = false;
    if (!attr_set) {
        cudaFuncSetAttribute(attn_f16_kernel,
                             cudaFuncAttributeMaxDynamicSharedMemorySize,
                             ATT_SMEM_BYTES);
        cudaFuncSetAttribute(gemm_f16_kernel<true>,
                             cudaFuncAttributeMaxDynamicSharedMemorySize,
                             GEMM_SMEM_BYTES);
        cudaFuncSetAttribute(gemm_f16_kernel<false>,
                             cudaFuncAttributeMaxDynamicSharedMemorySize,
                             GEMM_SMEM_BYTES);
        attr_set = true;
    }

    const int n4x = MROWS * D_DIM / 4;       // 4194304
    const int n4w = D_DIM * D_DIM / 4;       // 1048576

    // fp32 -> fp16 (RN)
    h_cvt_kernel<<<n4x / 256, 256>>>((const float4*)x, (uint2*)xh, n4x);
    dim3 cvt4_grid(n4w / 256, 4);
    h_cvt4_kernel<<<cvt4_grid, 256>>>((const float4*)wq, (const float4*)wk,
                                      (const float4*)wv, (const float4*)wo,
                                      (uint2*)wqkvh, (uint2*)woh, n4w);

    // Fused QKV projection: one GEMM, N = 6144, fp16 output.
    dim3 qkv_grid(NQKV / 128, MROWS / 128);   // (48, 64)
    gemm_f16_kernel<true><<<qkv_grid, 256, GEMM_SMEM_BYTES>>>(
        xh, wqkvh, qkvh, MROWS, NQKV, D_DIM);

    // fp16 tensor-core causal flash attention.
    dim3 attn_grid(S_LEN / QT, NHEAD, B_SZ);  // (16, 16, 4)
    attn_f16_kernel<<<attn_grid, 256, ATT_SMEM_BYTES>>>(qkvh, oh);

    // Output projection: fp32 output.
    dim3 out_grid(D_DIM / 128, MROWS / 128);  // (16, 64)
    gemm_f16_kernel<false><<<out_grid, 256, GEMM_SMEM_BYTES>>>(
        oh, woh, out, MROWS, D_DIM, D_DIM);
}

// round 16
// speedup vs baseline: 1.0079x; 1.0079x over previous
#include <cuda_runtime.h>
#include <cuda_fp16.h>
#include <math.h>
#include <cstdint>

// Problem constants
#define D_DIM 2048
#define S_LEN 2048
#define B_SZ  4
#define NHEAD 16
#define HD    128
#define MROWS (B_SZ * S_LEN)   // 8192
#define NQKV  (3 * D_DIM)      // 6144

// ---------------------------------------------------------------------------
// Scratch (device globals: allocation-guard-safe)
// ---------------------------------------------------------------------------
__device__ __half g_xh[(size_t)MROWS * D_DIM];
__device__ __half g_wqkvh[(size_t)NQKV * D_DIM];     // [wq; wk; wv] rows
__device__ __half g_woh[(size_t)D_DIM * D_DIM];
__device__ __half g_QKVh[(size_t)MROWS * NQKV];      // Q|K|V per row
__device__ __half g_Oh[(size_t)MROWS * D_DIM];

// ---------------------------------------------------------------------------
// Helpers
// ---------------------------------------------------------------------------
__device__ __forceinline__ uint32_t smem_u32(const void* p) {
    uint32_t a;
    asm("{ .reg .u64 t; cvta.to.shared.u64 t, %1; cvt.u32.u64 %0, t; }"
        : "=r"(a) : "l"(p));
    return a;
}
__device__ __forceinline__ void cp_async16(uint32_t saddr, const void* gaddr) {
    asm volatile("cp.async.cg.shared.global [%0], [%1], 16;"
                 :: "r"(saddr), "l"(gaddr) : "memory");
}
__device__ __forceinline__ void cp_commit() {
    asm volatile("cp.async.commit_group;" ::: "memory");
}
template <int N> __device__ __forceinline__ void cp_wait() {
    asm volatile("cp.async.wait_group %0;" :: "n"(N) : "memory");
}
__device__ __forceinline__ uint32_t pack_h2(float lo, float hi) {
    uint32_t r;
    asm("cvt.rn.f16x2.f32 %0, %1, %2;" : "=r"(r) : "f"(hi), "f"(lo));
    return r;
}
__device__ __forceinline__ float ex2f(float x) {
    float r;
    asm("ex2.approx.f32 %0, %1;" : "=f"(r) : "f"(x));
    return r;
}
__device__ __forceinline__ uint32_t ex2h2(uint32_t x) {
    uint32_t r;
    asm("ex2.approx.f16x2 %0, %1;" : "=r"(r) : "r"(x));
    return r;
}
__device__ __forceinline__ void mma_f16(float* d, const uint32_t* a, const uint32_t* b) {
    asm volatile(
        "mma.sync.aligned.m16n8k16.row.col.f32.f16.f16.f32 "
        "{%0,%1,%2,%3}, {%4,%5,%6,%7}, {%8,%9}, {%0,%1,%2,%3};"
        : "+f"(d[0]), "+f"(d[1]), "+f"(d[2]), "+f"(d[3])
        : "r"(a[0]), "r"(a[1]), "r"(a[2]), "r"(a[3]), "r"(b[0]), "r"(b[1]));
}
__device__ __forceinline__ void ldmx4(uint32_t& r0, uint32_t& r1,
                                      uint32_t& r2, uint32_t& r3, uint32_t addr) {
    asm volatile("ldmatrix.sync.aligned.m8n8.x4.shared.b16 {%0,%1,%2,%3}, [%4];"
                 : "=r"(r0), "=r"(r1), "=r"(r2), "=r"(r3) : "r"(addr));
}
__device__ __forceinline__ void ldmx4t(uint32_t& r0, uint32_t& r1,
                                       uint32_t& r2, uint32_t& r3, uint32_t addr) {
    asm volatile("ldmatrix.sync.aligned.m8n8.x4.trans.shared.b16 {%0,%1,%2,%3}, [%4];"
                 : "=r"(r0), "=r"(r1), "=r"(r2), "=r"(r3) : "r"(addr));
}

// ---------------------------------------------------------------------------
// fp32 -> fp16 conversion (RN), 4-wide ILP (MLP=4 hides DRAM latency)
// Launch with total threads == n4/4; thread i handles i, i+S, i+2S, i+3S.
// ---------------------------------------------------------------------------
__global__ void h_cvt_kernel(const float4* __restrict__ in,
                             uint2* __restrict__ out, int n4) {
    const int S = n4 >> 2;
    int i = blockIdx.x * blockDim.x + threadIdx.x;
    if (i < S) {
        float4 v0 = in[i];
        float4 v1 = in[i + S];
        float4 v2 = in[i + 2 * S];
        float4 v3 = in[i + 3 * S];
        out[i]         = make_uint2(pack_h2(v0.x, v0.y), pack_h2(v0.z, v0.w));
        out[i + S]     = make_uint2(pack_h2(v1.x, v1.y), pack_h2(v1.z, v1.w));
        out[i + 2 * S] = make_uint2(pack_h2(v2.x, v2.y), pack_h2(v2.z, v2.w));
        out[i + 3 * S] = make_uint2(pack_h2(v3.x, v3.y), pack_h2(v3.z, v3.w));
    }
}
// wq/wk/wv -> contiguous wqkvh regions; wo -> woh. One launch, 4-wide ILP.
__global__ void h_cvt4_kernel(const float4* __restrict__ s0,
                              const float4* __restrict__ s1,
                              const float4* __restrict__ s2,
                              const float4* __restrict__ s3,
                              uint2* __restrict__ out012,
                              uint2* __restrict__ out3, int n4each) {
    const int y = blockIdx.y;
    const float4* src = (y == 0) ? s0 : (y == 1) ? s1 : (y == 2) ? s2 : s3;
    uint2* dst = (y < 3) ? (out012 + (size_t)y * n4each) : out3;
    const int S = n4each >> 2;
    int i = blockIdx.x * blockDim.x + threadIdx.x;
    if (i < S) {
        float4 v0 = src[i];
        float4 v1 = src[i + S];
        float4 v2 = src[i + 2 * S];
        float4 v3 = src[i + 3 * S];
        dst[i]         = make_uint2(pack_h2(v0.x, v0.y), pack_h2(v0.z, v0.w));
        dst[i + S]     = make_uint2(pack_h2(v1.x, v1.y), pack_h2(v1.z, v1.w));
        dst[i + 2 * S] = make_uint2(pack_h2(v2.x, v2.y), pack_h2(v2.z, v2.w));
        dst[i + 3 * S] = make_uint2(pack_h2(v3.x, v3.y), pack_h2(v3.z, v3.w));
    }
}

// ---------------------------------------------------------------------------
// fp16 HMMA GEMM: C[M,N] = A[M,K] * B[N,K]^T, fp32 accumulate.
// 128x128 CTA, 256 threads, 8 warps (4m x 2n), warp tile 32x64, BK=64,
// 3-stage cp.async (2 CTAs/SM), incremental global pointers,
// batched ldmatrix per k-step, XOR-carrier addressing. (R10 config — FROZEN)
// ---------------------------------------------------------------------------
#define BKH 64
#define GTILE_BYTES (128 * BKH * 2)        // 16384
#define GSTAGE_BYTES (2 * GTILE_BYTES)     // 32768
#define GEMM_SMEM_BYTES (3 * GSTAGE_BYTES) // 98304

template <bool HALF_OUT>
__global__ __launch_bounds__(256, 2)
void gemm_f16_kernel(const __half* __restrict__ A,
                     const __half* __restrict__ B,
                     void* __restrict__ Cv,
                     int M, int N, int K)
{
    extern __shared__ char smem[];
    const uint32_t sbase = smem_u32(smem);
    const int tid  = threadIdx.x;
    const int wid  = tid >> 5;
    const int lane = tid & 31;
    const int wm   = wid >> 1;
    const int wn   = wid & 1;
    const int g    = lane >> 2;
    const int t    = lane & 3;
    const int bm0 = blockIdx.y * 128;
    const int bn0 = blockIdx.x * 128;

    const int lr = tid >> 3;
    const int lc = tid & 7;
    const __half* aptr = A + (size_t)(bm0 + lr) * K + lc * 8;
    const __half* bptr = B + (size_t)(bn0 + lr) * K + lc * 8;
    const uint32_t sAoff = (uint32_t)(lr * 128 + ((lc ^ (lr & 7)) << 4));
    const size_t gstep = (size_t)32 * K;

    const int lrow = lane & 15;
    const uint32_t chx = (uint32_t)(lane >> 4) << 4;
    const uint32_t relA0 = (uint32_t)((wm * 32 + lrow) * 128 + ((lrow & 7) << 4));
    const uint32_t relA1 = relA0 + 16 * 128;
    const uint32_t relB0 = (uint32_t)((wn * 64 + lrow) * 128 + ((lrow & 7) << 4));

    float acc[2][8][4];
    #pragma unroll
    for (int mt = 0; mt < 2; ++mt)
        #pragma unroll
        for (int nt = 0; nt < 8; ++nt)
            #pragma unroll
            for (int i = 0; i < 4; ++i) acc[mt][nt][i] = 0.0f;

    const int KT = K / BKH;

    #pragma unroll
    for (int st = 0; st < 2; ++st) {
        const uint32_t sb = sbase + (uint32_t)st * GSTAGE_BYTES + sAoff;
        #pragma unroll
        for (int i = 0; i < 4; ++i)
            cp_async16(sb + (uint32_t)(i * 4096), aptr + (size_t)i * gstep);
        #pragma unroll
        for (int i = 0; i < 4; ++i)
            cp_async16(sb + GTILE_BYTES + (uint32_t)(i * 4096), bptr + (size_t)i * gstep);
        cp_commit();
        aptr += BKH; bptr += BKH;
    }

    for (int kt = 0; kt < KT; ++kt) {
        const int s = kt % 3;
        if (kt == KT - 1) cp_wait<0>(); else cp_wait<1>();
        __syncthreads();

        if (kt + 2 < KT) {
            const uint32_t sb = sbase + (uint32_t)((kt + 2) % 3) * GSTAGE_BYTES + sAoff;
            #pragma unroll
            for (int i = 0; i < 4; ++i)
                cp_async16(sb + (uint32_t)(i * 4096), aptr + (size_t)i * gstep);
            #pragma unroll
            for (int i = 0; i < 4; ++i)
                cp_async16(sb + GTILE_BYTES + (uint32_t)(i * 4096), bptr + (size_t)i * gstep);
            cp_commit();
            aptr += BKH; bptr += BKH;
        }

        const uint32_t abase = sbase + (uint32_t)s * GSTAGE_BYTES;
        const uint32_t pA0 = (abase + relA0) ^ chx;
        const uint32_t pA1 = (abase + relA1) ^ chx;
        const uint32_t pB  = (abase + GTILE_BYTES + relB0) ^ chx;

        #pragma unroll
        for (int ks = 0; ks < 4; ++ks) {
            const uint32_t kx = (uint32_t)(ks * 32);
            uint32_t a0[4], a1[4], bf[4][4];
            ldmx4(a0[0], a0[1], a0[2], a0[3], pA0 ^ kx);
            ldmx4(a1[0], a1[1], a1[2], a1[3], pA1 ^ kx);
            #pragma unroll
            for (int nb = 0; nb < 4; ++nb)
                ldmx4(bf[nb][0], bf[nb][1], bf[nb][2], bf[nb][3],
                      (pB + (uint32_t)(nb * 2048)) ^ kx);
            #pragma unroll
            for (int nb = 0; nb < 4; ++nb) {
                uint32_t be[2] = {bf[nb][0], bf[nb][2]};
                uint32_t bo[2] = {bf[nb][1], bf[nb][3]};
                mma_f16(acc[0][2 * nb],     a0, be);
                mma_f16(acc[0][2 * nb + 1], a0, bo);
                mma_f16(acc[1][2 * nb],     a1, be);
                mma_f16(acc[1][2 * nb + 1], a1, bo);
            }
        }
    }

    #pragma unroll
    for (int mt = 0; mt < 2; ++mt) {
        int row = bm0 + wm * 32 + mt * 16 + g;
        #pragma unroll
        for (int nt = 0; nt < 8; ++nt) {
            int col = bn0 + wn * 64 + nt * 8 + t * 2;
            if (HALF_OUT) {
                __half* C = (__half*)Cv;
                *(uint32_t*)(C + (size_t)row * N + col) =
                    pack_h2(acc[mt][nt][0], acc[mt][nt][1]);
                *(uint32_t*)(C + (size_t)(row + 8) * N + col) =
                    pack_h2(acc[mt][nt][2], acc[mt][nt][3]);
            } else {
                float* C = (float*)Cv;
                *(float2*)(C + (size_t)row * N + col) =
                    make_float2(acc[mt][nt][0], acc[mt][nt][1]);
                *(float2*)(C + (size_t)(row + 8) * N + col) =
                    make_float2(acc[mt][nt][2], acc[mt][nt][3]);
            }
        }
    }
}

// ---------------------------------------------------------------------------
// fp16 tensor-core causal flash attention.
// f16x2 approx exp, tensor-core row sums, warp-uniform skip of O-rescale
// when no row max changed (alpha == 1 exactly -> multiply is a no-op).
// ---------------------------------------------------------------------------
#define QT  128
#define KVT 64
#define ATT_Q_BYTES  (QT * 256)                   // 32768
#define ATT_K_BYTES  (KVT * 256)                  // 16384
#define ATT_K_OFF    ATT_Q_BYTES
#define ATT_V_OFF    (ATT_K_OFF + 2 * ATT_K_BYTES)
#define ATT_SMEM_BYTES (ATT_V_OFF + 2 * ATT_K_BYTES)   // 98304

// scale * log2(e) = (1/sqrt(128)) * 1.4426950408889634
#define ATT_C1 0.12751744518362732f

__device__ __forceinline__ void attn_load_kv(uint32_t sbase, int stage,
                                             const __half* __restrict__ KV,
                                             size_t gbase, int k0, int tid) {
    #pragma unroll
    for (int i = 0; i < 4; ++i) {
        int idx = tid + i * 256;
        int r = idx >> 4;
        int c = idx & 15;
        uint32_t dst = sbase + ATT_K_OFF + (uint32_t)stage * ATT_K_BYTES
                     + (uint32_t)(r * 256 + ((c ^ (r & 7)) << 4));
        cp_async16(dst, KV + gbase + 2048 + (size_t)(k0 + r) * NQKV + c * 8);
    }
    #pragma unroll
    for (int i = 0; i < 4; ++i) {
        int idx = tid + i * 256;
        int r = idx >> 4;
        int c = idx & 15;
        uint32_t dst = sbase + ATT_V_OFF + (uint32_t)stage * ATT_K_BYTES
                     + (uint32_t)(r * 256 + ((c ^ (r & 7)) << 4));
        cp_async16(dst, KV + gbase + 4096 + (size_t)(k0 + r) * NQKV + c * 8);
    }
    cp_commit();
}

__global__ __launch_bounds__(256, 2)
void attn_f16_kernel(const __half* __restrict__ QKV,
                     __half* __restrict__ O)
{
    extern __shared__ char smc[];
    const uint32_t sbase = smem_u32(smc);

    const int tid  = threadIdx.x;
    const int wid  = tid >> 5;
    const int lane = tid & 31;
    const int g    = lane >> 2;
    const int t    = lane & 3;
    const int q0 = (gridDim.x - 1 - blockIdx.x) * QT;
    const int h  = blockIdx.y;
    const int b  = blockIdx.z;
    const size_t gbase = ((size_t)b * S_LEN) * NQKV + (size_t)h * HD;

    const int lrow = lane & 15;
    const uint32_t chx = (uint32_t)(lane >> 4) << 4;
    const int r0 = wid * 16;

    const uint32_t relQ = (uint32_t)((r0 + lrow) * 256 + ((lrow & 7) << 4));
    const uint32_t relK = (uint32_t)(lrow * 256 + ((lrow & 7) << 4));
    const uint32_t pQ = (sbase + relQ) ^ chx;

    // Q tile: 128 rows x 128 halves, swizzled.
    #pragma unroll
    for (int i = 0; i < 8; ++i) {
        int idx = tid + i * 256;
        int r = idx >> 4;
        int c = idx & 15;
        uint32_t dst = sbase + (uint32_t)(r * 256 + ((c ^ (r & 7)) << 4));
        cp_async16(dst, QKV + gbase + (size_t)(q0 + r) * NQKV + c * 8);
    }
    attn_load_kv(sbase, 0, QKV, gbase, 0, tid);

    float o[16][4];
    #pragma unroll
    for (int j = 0; j < 16; ++j)
        #pragma unroll
        for (int i = 0; i < 4; ++i) o[j][i] = 0.0f;
    float m2[2] = {-INFINITY, -INFINITY};
    float l2[2] = {0.0f, 0.0f};

    const int ntiles = q0 / KVT + 2;

    for (int tt = 0; tt < ntiles; ++tt) {
        const int s = tt & 1;
        cp_wait<0>();
        __syncthreads();
        if (tt + 1 < ntiles)
            attn_load_kv(sbase, s ^ 1, QKV, gbase, (tt + 1) * KVT, tid);

        const int kk0 = tt * KVT;
        if (kk0 <= q0 + r0 + 15) {
            const uint32_t kb = sbase + ATT_K_OFF + (uint32_t)s * ATT_K_BYTES;
            const uint32_t vb = sbase + ATT_V_OFF + (uint32_t)s * ATT_K_BYTES;
            const uint32_t pK = (kb + relK) ^ chx;
            const uint32_t pV = (vb + relK) ^ chx;

            // ---- QK^T: 16x64 scores per warp ----
            float sc[8][4];
            #pragma unroll
            for (int j = 0; j < 8; ++j)
                #pragma unroll
                for (int i = 0; i < 4; ++i) sc[j][i] = 0.0f;

            #pragma unroll
            for (int ks = 0; ks < 8; ++ks) {
                const uint32_t kx = (uint32_t)(ks * 32);
                uint32_t a[4];
                ldmx4(a[0], a[1], a[2], a[3], pQ ^ kx);
                #pragma unroll
                for (int nb = 0; nb < 4; ++nb) {
                    uint32_t bf[4];
                    ldmx4(bf[0], bf[1], bf[2], bf[3],
                          (pK + (uint32_t)(nb * 4096)) ^ kx);
                    uint32_t be[2] = {bf[0], bf[2]};
                    uint32_t bo[2] = {bf[1], bf[3]};
                    mma_f16(sc[2 * nb],     a, be);
                    mma_f16(sc[2 * nb + 1], a, bo);
                }
            }

            // ---- causal mask (diagonal tiles only) ----
            if (kk0 + KVT - 1 > q0 + r0) {
                #pragma unroll
                for (int j = 0; j < 8; ++j) {
                    int colb = kk0 + j * 8 + 2 * t;
                    int rowa = q0 + r0 + g;
                    if (colb     > rowa)     sc[j][0] = -INFINITY;
                    if (colb + 1 > rowa)     sc[j][1] = -INFINITY;
                    if (colb     > rowa + 8) sc[j][2] = -INFINITY;
                    if (colb + 1 > rowa + 8) sc[j][3] = -INFINITY;
                }
            }

            // ---- online max + alpha (rows g and g+8) ----
            float alpha2[2], base2[2];
            #pragma unroll
            for (int half = 0; half < 2; ++half) {
                const int i0 = half * 2;
                float rmax = -INFINITY;
                #pragma unroll
                for (int j = 0; j < 8; ++j)
                    rmax = fmaxf(rmax, fmaxf(sc[j][i0], sc[j][i0 + 1]));
                rmax = fmaxf(rmax, __shfl_xor_sync(0xffffffffu, rmax, 1));
                rmax = fmaxf(rmax, __shfl_xor_sync(0xffffffffu, rmax, 2));
                float mold = m2[half];
                float mnew = fmaxf(mold, rmax);
                alpha2[half] = ex2f((mold - mnew) * ATT_C1);
                m2[half] = mnew;
                base2[half] = mnew * ATT_C1;
            }
            // Rescale only if some row max actually changed (alpha != 1).
            // alpha == 1.0f exactly when mold == mnew; x*1.0f is a no-op,
            // so skipping is bit-identical. Warp-uniform branch.
            if (!__all_sync(0xffffffffu,
                            (alpha2[0] == 1.0f) && (alpha2[1] == 1.0f))) {
                #pragma unroll
                for (int j = 0; j < 16; ++j) {
                    o[j][0] *= alpha2[0]; o[j][1] *= alpha2[0];
                    o[j][2] *= alpha2[1]; o[j][3] *= alpha2[1];
                }
            }

            // ---- exp via f16x2: P fragments built directly ----
            uint32_t ph[8][2];
            #pragma unroll
            for (int j = 0; j < 8; ++j) {
                ph[j][0] = ex2h2(pack_h2(fmaf(sc[j][0], ATT_C1, -base2[0]),
                                         fmaf(sc[j][1], ATT_C1, -base2[0])));
                ph[j][1] = ex2h2(pack_h2(fmaf(sc[j][2], ATT_C1, -base2[1]),
                                         fmaf(sc[j][3], ATT_C1, -base2[1])));
            }

            // ---- PV + row-sum MMAs ----
            float racc[4] = {0.0f, 0.0f, 0.0f, 0.0f};
            const uint32_t ones2[2] = {0x3C003C00u, 0x3C003C00u};
            #pragma unroll
            for (int kk = 0; kk < 4; ++kk) {
                uint32_t a[4] = {ph[2 * kk][0], ph[2 * kk][1],
                                 ph[2 * kk + 1][0], ph[2 * kk + 1][1]};
                mma_f16(racc, a, ones2);       // row sums (all cols identical)
                const uint32_t pVk = pV + (uint32_t)(kk * 4096);
                #pragma unroll
                for (int pair = 0; pair < 8; ++pair) {
                    uint32_t v0, v1, v2, v3;
                    ldmx4t(v0, v1, v2, v3, pVk ^ (uint32_t)(pair * 32));
                    uint32_t b0[2] = {v0, v1};
                    uint32_t b1[2] = {v2, v3};
                    mma_f16(o[pair * 2],     a, b0);
                    mma_f16(o[pair * 2 + 1], a, b1);
                }
            }
            l2[0] = l2[0] * alpha2[0] + racc[0];
            l2[1] = l2[1] * alpha2[1] + racc[2];
        }
    }

    // ---- epilogue: normalize, store fp16 O [MROWS x D_DIM] ----
    const float inv0 = 1.0f / l2[0];
    const float inv1 = 1.0f / l2[1];
    const int rowa = q0 + r0 + g;
    const size_t obase = ((size_t)b * S_LEN) * D_DIM + (size_t)h * HD;
    #pragma unroll
    for (int j = 0; j < 16; ++j) {
        int col = j * 8 + 2 * t;
        *(uint32_t*)(O + obase + (size_t)rowa * D_DIM + col) =
            pack_h2(o[j][0] * inv0, o[j][1] * inv0);
        *(uint32_t*)(O + obase + (size_t)(rowa + 8) * D_DIM + col) =
            pack_h2(o[j][2] * inv1, o[j][3] * inv1);
    }
}

// ---------------------------------------------------------------------------
// Launch
// ---------------------------------------------------------------------------
extern "C" void kernel_launch(void* const* d_in, const int* in_sizes, int n_in,
                              void* d_out, int out_size)
{
    const float* x  = (const float*)d_in[0];
    const float* wq = (const float*)d_in[1];
    const float* wk = (const float*)d_in[2];
    const float* wv = (const float*)d_in[3];
    const float* wo = (const float*)d_in[4];
    float* out = (float*)d_out;

    __half *xh, *wqkvh, *woh, *qkvh, *oh;
    cudaGetSymbolAddress((void**)&xh,    g_xh);
    cudaGetSymbolAddress((void**)&wqkvh, g_wqkvh);
    cudaGetSymbolAddress((void**)&woh,   g_woh);
    cudaGetSymbolAddress((void**)&qkvh,  g_QKVh);
    cudaGetSymbolAddress((void**)&oh,    g_Oh);

    static bool attr_set = false;
    if (!attr_set) {
        cudaFuncSetAttribute(attn_f16_kernel,
                             cudaFuncAttributeMaxDynamicSharedMemorySize,
                             ATT_SMEM_BYTES);
        cudaFuncSetAttribute(gemm_f16_kernel<true>,
                             cudaFuncAttributeMaxDynamicSharedMemorySize,
                             GEMM_SMEM_BYTES);
        cudaFuncSetAttribute(gemm_f16_kernel<false>,
                             cudaFuncAttributeMaxDynamicSharedMemorySize,
                             GEMM_SMEM_BYTES);
        attr_set = true;
    }

    const int n4x = MROWS * D_DIM / 4;       // 4194304
    const int n4w = D_DIM * D_DIM / 4;       // 1048576

    // fp32 -> fp16 (RN), 4-wide ILP: total threads = n4/4.
    h_cvt_kernel<<<n4x / 1024, 256>>>((const float4*)x, (uint2*)xh, n4x);
    dim3 cvt4_grid(n4w / 1024, 4);
    h_cvt4_kernel<<<cvt4_grid, 256>>>((const float4*)wq, (const float4*)wk,
                                      (const float4*)wv, (const float4*)wo,
                                      (uint2*)wqkvh, (uint2*)woh, n4w);

    // Fused QKV projection: one GEMM, N = 6144, fp16 output.
    dim3 qkv_grid(NQKV / 128, MROWS / 128);   // (48, 64)
    gemm_f16_kernel<true><<<qkv_grid, 256, GEMM_SMEM_BYTES>>>(
        xh, wqkvh, qkvh, MROWS, NQKV, D_DIM);

    // fp16 tensor-core causal flash attention.
    dim3 attn_grid(S_LEN / QT, NHEAD, B_SZ);  // (16, 16, 4)
    attn_f16_kernel<<<attn_grid, 256, ATT_SMEM_BYTES>>>(qkvh, oh);

    // Output projection: fp32 output.
    dim3 out_grid(D_DIM / 128, MROWS / 128);  // (16, 64)
    gemm_f16_kernel<false><<<out_grid, 256, GEMM_SMEM_BYTES>>>(
        oh, woh, out, MROWS, D_DIM, D_DIM);
}

// round 17
// speedup vs baseline: 1.0100x; 1.0020x over previous
#include <cuda_runtime.h>
#include <cuda_fp16.h>
#include <math.h>
#include <cstdint>

// Problem constants
#define D_DIM 2048
#define S_LEN 2048
#define B_SZ  4
#define NHEAD 16
#define HD    128
#define MROWS (B_SZ * S_LEN)   // 8192
#define NQKV  (3 * D_DIM)      // 6144

// ---------------------------------------------------------------------------
// Scratch (device globals: allocation-guard-safe)
// ---------------------------------------------------------------------------
__device__ __half g_xh[(size_t)MROWS * D_DIM];
__device__ __half g_wqkvh[(size_t)NQKV * D_DIM];     // [wq; wk; wv] rows
__device__ __half g_woh[(size_t)D_DIM * D_DIM];
__device__ __half g_QKVh[(size_t)MROWS * NQKV];      // Q|K|V per row
__device__ __half g_Oh[(size_t)MROWS * D_DIM];

// ---------------------------------------------------------------------------
// Helpers
// ---------------------------------------------------------------------------
__device__ __forceinline__ uint32_t smem_u32(const void* p) {
    uint32_t a;
    asm("{ .reg .u64 t; cvta.to.shared.u64 t, %1; cvt.u32.u64 %0, t; }"
        : "=r"(a) : "l"(p));
    return a;
}
__device__ __forceinline__ void cp_async16(uint32_t saddr, const void* gaddr) {
    asm volatile("cp.async.cg.shared.global [%0], [%1], 16;"
                 :: "r"(saddr), "l"(gaddr) : "memory");
}
__device__ __forceinline__ void cp_commit() {
    asm volatile("cp.async.commit_group;" ::: "memory");
}
template <int N> __device__ __forceinline__ void cp_wait() {
    asm volatile("cp.async.wait_group %0;" :: "n"(N) : "memory");
}
__device__ __forceinline__ uint32_t pack_h2(float lo, float hi) {
    uint32_t r;
    asm("cvt.rn.f16x2.f32 %0, %1, %2;" : "=r"(r) : "f"(hi), "f"(lo));
    return r;
}
__device__ __forceinline__ float ex2f(float x) {
    float r;
    asm("ex2.approx.f32 %0, %1;" : "=f"(r) : "f"(x));
    return r;
}
__device__ __forceinline__ uint32_t ex2h2(uint32_t x) {
    uint32_t r;
    asm("ex2.approx.f16x2 %0, %1;" : "=r"(r) : "r"(x));
    return r;
}
__device__ __forceinline__ void mma_f16(float* d, const uint32_t* a, const uint32_t* b) {
    asm volatile(
        "mma.sync.aligned.m16n8k16.row.col.f32.f16.f16.f32 "
        "{%0,%1,%2,%3}, {%4,%5,%6,%7}, {%8,%9}, {%0,%1,%2,%3};"
        : "+f"(d[0]), "+f"(d[1]), "+f"(d[2]), "+f"(d[3])
        : "r"(a[0]), "r"(a[1]), "r"(a[2]), "r"(a[3]), "r"(b[0]), "r"(b[1]));
}
__device__ __forceinline__ void ldmx4(uint32_t& r0, uint32_t& r1,
                                      uint32_t& r2, uint32_t& r3, uint32_t addr) {
    asm volatile("ldmatrix.sync.aligned.m8n8.x4.shared.b16 {%0,%1,%2,%3}, [%4];"
                 : "=r"(r0), "=r"(r1), "=r"(r2), "=r"(r3) : "r"(addr));
}
__device__ __forceinline__ void ldmx4t(uint32_t& r0, uint32_t& r1,
                                       uint32_t& r2, uint32_t& r3, uint32_t addr) {
    asm volatile("ldmatrix.sync.aligned.m8n8.x4.trans.shared.b16 {%0,%1,%2,%3}, [%4];"
                 : "=r"(r0), "=r"(r1), "=r"(r2), "=r"(r3) : "r"(addr));
}

// ---------------------------------------------------------------------------
// fp32 -> fp16 conversion (RN), 4-wide ILP (MLP=4 hides DRAM latency)
// ---------------------------------------------------------------------------
__global__ void h_cvt_kernel(const float4* __restrict__ in,
                             uint2* __restrict__ out, int n4) {
    const int S = n4 >> 2;
    int i = blockIdx.x * blockDim.x + threadIdx.x;
    if (i < S) {
        float4 v0 = in[i];
        float4 v1 = in[i + S];
        float4 v2 = in[i + 2 * S];
        float4 v3 = in[i + 3 * S];
        out[i]         = make_uint2(pack_h2(v0.x, v0.y), pack_h2(v0.z, v0.w));
        out[i + S]     = make_uint2(pack_h2(v1.x, v1.y), pack_h2(v1.z, v1.w));
        out[i + 2 * S] = make_uint2(pack_h2(v2.x, v2.y), pack_h2(v2.z, v2.w));
        out[i + 3 * S] = make_uint2(pack_h2(v3.x, v3.y), pack_h2(v3.z, v3.w));
    }
}
__global__ void h_cvt4_kernel(const float4* __restrict__ s0,
                              const float4* __restrict__ s1,
                              const float4* __restrict__ s2,
                              const float4* __restrict__ s3,
                              uint2* __restrict__ out012,
                              uint2* __restrict__ out3, int n4each) {
    const int y = blockIdx.y;
    const float4* src = (y == 0) ? s0 : (y == 1) ? s1 : (y == 2) ? s2 : s3;
    uint2* dst = (y < 3) ? (out012 + (size_t)y * n4each) : out3;
    const int S = n4each >> 2;
    int i = blockIdx.x * blockDim.x + threadIdx.x;
    if (i < S) {
        float4 v0 = src[i];
        float4 v1 = src[i + S];
        float4 v2 = src[i + 2 * S];
        float4 v3 = src[i + 3 * S];
        dst[i]         = make_uint2(pack_h2(v0.x, v0.y), pack_h2(v0.z, v0.w));
        dst[i + S]     = make_uint2(pack_h2(v1.x, v1.y), pack_h2(v1.z, v1.w));
        dst[i + 2 * S] = make_uint2(pack_h2(v2.x, v2.y), pack_h2(v2.z, v2.w));
        dst[i + 3 * S] = make_uint2(pack_h2(v3.x, v3.y), pack_h2(v3.z, v3.w));
    }
}

// ---------------------------------------------------------------------------
// fp16 HMMA GEMM (R10 config — FROZEN)
// ---------------------------------------------------------------------------
#define BKH 64
#define GTILE_BYTES (128 * BKH * 2)        // 16384
#define GSTAGE_BYTES (2 * GTILE_BYTES)     // 32768
#define GEMM_SMEM_BYTES (3 * GSTAGE_BYTES) // 98304

template <bool HALF_OUT>
__global__ __launch_bounds__(256, 2)
void gemm_f16_kernel(const __half* __restrict__ A,
                     const __half* __restrict__ B,
                     void* __restrict__ Cv,
                     int M, int N, int K)
{
    extern __shared__ char smem[];
    const uint32_t sbase = smem_u32(smem);
    const int tid  = threadIdx.x;
    const int wid  = tid >> 5;
    const int lane = tid & 31;
    const int wm   = wid >> 1;
    const int wn   = wid & 1;
    const int g    = lane >> 2;
    const int t    = lane & 3;
    const int bm0 = blockIdx.y * 128;
    const int bn0 = blockIdx.x * 128;

    const int lr = tid >> 3;
    const int lc = tid & 7;
    const __half* aptr = A + (size_t)(bm0 + lr) * K + lc * 8;
    const __half* bptr = B + (size_t)(bn0 + lr) * K + lc * 8;
    const uint32_t sAoff = (uint32_t)(lr * 128 + ((lc ^ (lr & 7)) << 4));
    const size_t gstep = (size_t)32 * K;

    const int lrow = lane & 15;
    const uint32_t chx = (uint32_t)(lane >> 4) << 4;
    const uint32_t relA0 = (uint32_t)((wm * 32 + lrow) * 128 + ((lrow & 7) << 4));
    const uint32_t relA1 = relA0 + 16 * 128;
    const uint32_t relB0 = (uint32_t)((wn * 64 + lrow) * 128 + ((lrow & 7) << 4));

    float acc[2][8][4];
    #pragma unroll
    for (int mt = 0; mt < 2; ++mt)
        #pragma unroll
        for (int nt = 0; nt < 8; ++nt)
            #pragma unroll
            for (int i = 0; i < 4; ++i) acc[mt][nt][i] = 0.0f;

    const int KT = K / BKH;

    #pragma unroll
    for (int st = 0; st < 2; ++st) {
        const uint32_t sb = sbase + (uint32_t)st * GSTAGE_BYTES + sAoff;
        #pragma unroll
        for (int i = 0; i < 4; ++i)
            cp_async16(sb + (uint32_t)(i * 4096), aptr + (size_t)i * gstep);
        #pragma unroll
        for (int i = 0; i < 4; ++i)
            cp_async16(sb + GTILE_BYTES + (uint32_t)(i * 4096), bptr + (size_t)i * gstep);
        cp_commit();
        aptr += BKH; bptr += BKH;
    }

    for (int kt = 0; kt < KT; ++kt) {
        const int s = kt % 3;
        if (kt == KT - 1) cp_wait<0>(); else cp_wait<1>();
        __syncthreads();

        if (kt + 2 < KT) {
            const uint32_t sb = sbase + (uint32_t)((kt + 2) % 3) * GSTAGE_BYTES + sAoff;
            #pragma unroll
            for (int i = 0; i < 4; ++i)
                cp_async16(sb + (uint32_t)(i * 4096), aptr + (size_t)i * gstep);
            #pragma unroll
            for (int i = 0; i < 4; ++i)
                cp_async16(sb + GTILE_BYTES + (uint32_t)(i * 4096), bptr + (size_t)i * gstep);
            cp_commit();
            aptr += BKH; bptr += BKH;
        }

        const uint32_t abase = sbase + (uint32_t)s * GSTAGE_BYTES;
        const uint32_t pA0 = (abase + relA0) ^ chx;
        const uint32_t pA1 = (abase + relA1) ^ chx;
        const uint32_t pB  = (abase + GTILE_BYTES + relB0) ^ chx;

        #pragma unroll
        for (int ks = 0; ks < 4; ++ks) {
            const uint32_t kx = (uint32_t)(ks * 32);
            uint32_t a0[4], a1[4], bf[4][4];
            ldmx4(a0[0], a0[1], a0[2], a0[3], pA0 ^ kx);
            ldmx4(a1[0], a1[1], a1[2], a1[3], pA1 ^ kx);
            #pragma unroll
            for (int nb = 0; nb < 4; ++nb)
                ldmx4(bf[nb][0], bf[nb][1], bf[nb][2], bf[nb][3],
                      (pB + (uint32_t)(nb * 2048)) ^ kx);
            #pragma unroll
            for (int nb = 0; nb < 4; ++nb) {
                uint32_t be[2] = {bf[nb][0], bf[nb][2]};
                uint32_t bo[2] = {bf[nb][1], bf[nb][3]};
                mma_f16(acc[0][2 * nb],     a0, be);
                mma_f16(acc[0][2 * nb + 1], a0, bo);
                mma_f16(acc[1][2 * nb],     a1, be);
                mma_f16(acc[1][2 * nb + 1], a1, bo);
            }
        }
    }

    #pragma unroll
    for (int mt = 0; mt < 2; ++mt) {
        int row = bm0 + wm * 32 + mt * 16 + g;
        #pragma unroll
        for (int nt = 0; nt < 8; ++nt) {
            int col = bn0 + wn * 64 + nt * 8 + t * 2;
            if (HALF_OUT) {
                __half* C = (__half*)Cv;
                *(uint32_t*)(C + (size_t)row * N + col) =
                    pack_h2(acc[mt][nt][0], acc[mt][nt][1]);
                *(uint32_t*)(C + (size_t)(row + 8) * N + col) =
                    pack_h2(acc[mt][nt][2], acc[mt][nt][3]);
            } else {
                float* C = (float*)Cv;
                *(float2*)(C + (size_t)row * N + col) =
                    make_float2(acc[mt][nt][0], acc[mt][nt][1]);
                *(float2*)(C + (size_t)(row + 8) * N + col) =
                    make_float2(acc[mt][nt][2], acc[mt][nt][3]);
            }
        }
    }
}

// ---------------------------------------------------------------------------
// fp16 tensor-core causal flash attention.
// R16 + batched fragment loads in QK (2-wide) and PV (4-wide) loops —
// pure reordering, bit-identical results, fewer exposed LDSM latencies.
// ---------------------------------------------------------------------------
#define QT  128
#define KVT 64
#define ATT_Q_BYTES  (QT * 256)                   // 32768
#define ATT_K_BYTES  (KVT * 256)                  // 16384
#define ATT_K_OFF    ATT_Q_BYTES
#define ATT_V_OFF    (ATT_K_OFF + 2 * ATT_K_BYTES)
#define ATT_SMEM_BYTES (ATT_V_OFF + 2 * ATT_K_BYTES)   // 98304

// scale * log2(e) = (1/sqrt(128)) * 1.4426950408889634
#define ATT_C1 0.12751744518362732f

__device__ __forceinline__ void attn_load_kv(uint32_t sbase, int stage,
                                             const __half* __restrict__ KV,
                                             size_t gbase, int k0, int tid) {
    #pragma unroll
    for (int i = 0; i < 4; ++i) {
        int idx = tid + i * 256;
        int r = idx >> 4;
        int c = idx & 15;
        uint32_t dst = sbase + ATT_K_OFF + (uint32_t)stage * ATT_K_BYTES
                     + (uint32_t)(r * 256 + ((c ^ (r & 7)) << 4));
        cp_async16(dst, KV + gbase + 2048 + (size_t)(k0 + r) * NQKV + c * 8);
    }
    #pragma unroll
    for (int i = 0; i < 4; ++i) {
        int idx = tid + i * 256;
        int r = idx >> 4;
        int c = idx & 15;
        uint32_t dst = sbase + ATT_V_OFF + (uint32_t)stage * ATT_K_BYTES
                     + (uint32_t)(r * 256 + ((c ^ (r & 7)) << 4));
        cp_async16(dst, KV + gbase + 4096 + (size_t)(k0 + r) * NQKV + c * 8);
    }
    cp_commit();
}

__global__ __launch_bounds__(256, 2)
void attn_f16_kernel(const __half* __restrict__ QKV,
                     __half* __restrict__ O)
{
    extern __shared__ char smc[];
    const uint32_t sbase = smem_u32(smc);

    const int tid  = threadIdx.x;
    const int wid  = tid >> 5;
    const int lane = tid & 31;
    const int g    = lane >> 2;
    const int t    = lane & 3;
    const int q0 = (gridDim.x - 1 - blockIdx.x) * QT;
    const int h  = blockIdx.y;
    const int b  = blockIdx.z;
    const size_t gbase = ((size_t)b * S_LEN) * NQKV + (size_t)h * HD;

    const int lrow = lane & 15;
    const uint32_t chx = (uint32_t)(lane >> 4) << 4;
    const int r0 = wid * 16;

    const uint32_t relQ = (uint32_t)((r0 + lrow) * 256 + ((lrow & 7) << 4));
    const uint32_t relK = (uint32_t)(lrow * 256 + ((lrow & 7) << 4));
    const uint32_t pQ = (sbase + relQ) ^ chx;

    // Q tile: 128 rows x 128 halves, swizzled.
    #pragma unroll
    for (int i = 0; i < 8; ++i) {
        int idx = tid + i * 256;
        int r = idx >> 4;
        int c = idx & 15;
        uint32_t dst = sbase + (uint32_t)(r * 256 + ((c ^ (r & 7)) << 4));
        cp_async16(dst, QKV + gbase + (size_t)(q0 + r) * NQKV + c * 8);
    }
    attn_load_kv(sbase, 0, QKV, gbase, 0, tid);

    float o[16][4];
    #pragma unroll
    for (int j = 0; j < 16; ++j)
        #pragma unroll
        for (int i = 0; i < 4; ++i) o[j][i] = 0.0f;
    float m2[2] = {-INFINITY, -INFINITY};
    float l2[2] = {0.0f, 0.0f};

    const int ntiles = q0 / KVT + 2;

    for (int tt = 0; tt < ntiles; ++tt) {
        const int s = tt & 1;
        cp_wait<0>();
        __syncthreads();
        if (tt + 1 < ntiles)
            attn_load_kv(sbase, s ^ 1, QKV, gbase, (tt + 1) * KVT, tid);

        const int kk0 = tt * KVT;
        if (kk0 <= q0 + r0 + 15) {
            const uint32_t kb = sbase + ATT_K_OFF + (uint32_t)s * ATT_K_BYTES;
            const uint32_t vb = sbase + ATT_V_OFF + (uint32_t)s * ATT_K_BYTES;
            const uint32_t pK = (kb + relK) ^ chx;
            const uint32_t pV = (vb + relK) ^ chx;

            // ---- QK^T: 16x64 scores per warp (batched B frags, 2-wide) ----
            float sc[8][4];
            #pragma unroll
            for (int j = 0; j < 8; ++j)
                #pragma unroll
                for (int i = 0; i < 4; ++i) sc[j][i] = 0.0f;

            #pragma unroll
            for (int ks = 0; ks < 8; ++ks) {
                const uint32_t kx = (uint32_t)(ks * 32);
                uint32_t a[4];
                ldmx4(a[0], a[1], a[2], a[3], pQ ^ kx);
                #pragma unroll
                for (int nh = 0; nh < 2; ++nh) {
                    uint32_t bf[2][4];
                    #pragma unroll
                    for (int nb = 0; nb < 2; ++nb)
                        ldmx4(bf[nb][0], bf[nb][1], bf[nb][2], bf[nb][3],
                              (pK + (uint32_t)((nh * 2 + nb) * 4096)) ^ kx);
                    #pragma unroll
                    for (int nb = 0; nb < 2; ++nb) {
                        const int j = (nh * 2 + nb) * 2;
                        uint32_t be[2] = {bf[nb][0], bf[nb][2]};
                        uint32_t bo[2] = {bf[nb][1], bf[nb][3]};
                        mma_f16(sc[j],     a, be);
                        mma_f16(sc[j + 1], a, bo);
                    }
                }
            }

            // ---- causal mask (diagonal tiles only) ----
            if (kk0 + KVT - 1 > q0 + r0) {
                #pragma unroll
                for (int j = 0; j < 8; ++j) {
                    int colb = kk0 + j * 8 + 2 * t;
                    int rowa = q0 + r0 + g;
                    if (colb     > rowa)     sc[j][0] = -INFINITY;
                    if (colb + 1 > rowa)     sc[j][1] = -INFINITY;
                    if (colb     > rowa + 8) sc[j][2] = -INFINITY;
                    if (colb + 1 > rowa + 8) sc[j][3] = -INFINITY;
                }
            }

            // ---- online max + alpha (rows g and g+8) ----
            float alpha2[2], base2[2];
            #pragma unroll
            for (int half = 0; half < 2; ++half) {
                const int i0 = half * 2;
                float rmax = -INFINITY;
                #pragma unroll
                for (int j = 0; j < 8; ++j)
                    rmax = fmaxf(rmax, fmaxf(sc[j][i0], sc[j][i0 + 1]));
                rmax = fmaxf(rmax, __shfl_xor_sync(0xffffffffu, rmax, 1));
                rmax = fmaxf(rmax, __shfl_xor_sync(0xffffffffu, rmax, 2));
                float mold = m2[half];
                float mnew = fmaxf(mold, rmax);
                alpha2[half] = ex2f((mold - mnew) * ATT_C1);
                m2[half] = mnew;
                base2[half] = mnew * ATT_C1;
            }
            // Skip O-rescale when no row max changed (alpha == 1 exactly).
            if (!__all_sync(0xffffffffu,
                            (alpha2[0] == 1.0f) && (alpha2[1] == 1.0f))) {
                #pragma unroll
                for (int j = 0; j < 16; ++j) {
                    o[j][0] *= alpha2[0]; o[j][1] *= alpha2[0];
                    o[j][2] *= alpha2[1]; o[j][3] *= alpha2[1];
                }
            }

            // ---- exp via f16x2: P fragments built directly ----
            uint32_t ph[8][2];
            #pragma unroll
            for (int j = 0; j < 8; ++j) {
                ph[j][0] = ex2h2(pack_h2(fmaf(sc[j][0], ATT_C1, -base2[0]),
                                         fmaf(sc[j][1], ATT_C1, -base2[0])));
                ph[j][1] = ex2h2(pack_h2(fmaf(sc[j][2], ATT_C1, -base2[1]),
                                         fmaf(sc[j][3], ATT_C1, -base2[1])));
            }

            // ---- PV + row-sum MMAs (batched V frags, 4-wide) ----
            float racc[4] = {0.0f, 0.0f, 0.0f, 0.0f};
            const uint32_t ones2[2] = {0x3C003C00u, 0x3C003C00u};
            #pragma unroll
            for (int kk = 0; kk < 4; ++kk) {
                uint32_t a[4] = {ph[2 * kk][0], ph[2 * kk][1],
                                 ph[2 * kk + 1][0], ph[2 * kk + 1][1]};
                mma_f16(racc, a, ones2);       // row sums (all cols identical)
                const uint32_t pVk = pV + (uint32_t)(kk * 4096);
                #pragma unroll
                for (int grp = 0; grp < 2; ++grp) {
                    uint32_t vf[4][4];
                    #pragma unroll
                    for (int p2 = 0; p2 < 4; ++p2)
                        ldmx4t(vf[p2][0], vf[p2][1], vf[p2][2], vf[p2][3],
                               pVk ^ (uint32_t)((grp * 4 + p2) * 32));
                    #pragma unroll
                    for (int p2 = 0; p2 < 4; ++p2) {
                        const int pair = grp * 4 + p2;
                        uint32_t b0[2] = {vf[p2][0], vf[p2][1]};
                        uint32_t b1[2] = {vf[p2][2], vf[p2][3]};
                        mma_f16(o[pair * 2],     a, b0);
                        mma_f16(o[pair * 2 + 1], a, b1);
                    }
                }
            }
            l2[0] = l2[0] * alpha2[0] + racc[0];
            l2[1] = l2[1] * alpha2[1] + racc[2];
        }
    }

    // ---- epilogue: normalize, store fp16 O [MROWS x D_DIM] ----
    const float inv0 = 1.0f / l2[0];
    const float inv1 = 1.0f / l2[1];
    const int rowa = q0 + r0 + g;
    const size_t obase = ((size_t)b * S_LEN) * D_DIM + (size_t)h * HD;
    #pragma unroll
    for (int j = 0; j < 16; ++j) {
        int col = j * 8 + 2 * t;
        *(uint32_t*)(O + obase + (size_t)rowa * D_DIM + col) =
            pack_h2(o[j][0] * inv0, o[j][1] * inv0);
        *(uint32_t*)(O + obase + (size_t)(rowa + 8) * D_DIM + col) =
            pack_h2(o[j][2] * inv1, o[j][3] * inv1);
    }
}

// ---------------------------------------------------------------------------
// Launch
// ---------------------------------------------------------------------------
extern "C" void kernel_launch(void* const* d_in, const int* in_sizes, int n_in,
                              void* d_out, int out_size)
{
    const float* x  = (const float*)d_in[0];
    const float* wq = (const float*)d_in[1];
    const float* wk = (const float*)d_in[2];
    const float* wv = (const float*)d_in[3];
    const float* wo = (const float*)d_in[4];
    float* out = (float*)d_out;

    __half *xh, *wqkvh, *woh, *qkvh, *oh;
    cudaGetSymbolAddress((void**)&xh,    g_xh);
    cudaGetSymbolAddress((void**)&wqkvh, g_wqkvh);
    cudaGetSymbolAddress((void**)&woh,   g_woh);
    cudaGetSymbolAddress((void**)&qkvh,  g_QKVh);
    cudaGetSymbolAddress((void**)&oh,    g_Oh);

    static bool attr_set = false;
    if (!attr_set) {
        cudaFuncSetAttribute(attn_f16_kernel,
                             cudaFuncAttributeMaxDynamicSharedMemorySize,
                             ATT_SMEM_BYTES);
        cudaFuncSetAttribute(gemm_f16_kernel<true>,
                             cudaFuncAttributeMaxDynamicSharedMemorySize,
                             GEMM_SMEM_BYTES);
        cudaFuncSetAttribute(gemm_f16_kernel<false>,
                             cudaFuncAttributeMaxDynamicSharedMemorySize,
                             GEMM_SMEM_BYTES);
        attr_set = true;
    }

    const int n4x = MROWS * D_DIM / 4;       // 4194304
    const int n4w = D_DIM * D_DIM / 4;       // 1048576

    // fp32 -> fp16 (RN), 4-wide ILP.
    h_cvt_kernel<<<n4x / 1024, 256>>>((const float4*)x, (uint2*)xh, n4x);
    dim3 cvt4_grid(n4w / 1024, 4);
    h_cvt4_kernel<<<cvt4_grid, 256>>>((const float4*)wq, (const float4*)wk,
                                      (const float4*)wv, (const float4*)wo,
                                      (uint2*)wqkvh, (uint2*)woh, n4w);

    // Fused QKV projection: one GEMM, N = 6144, fp16 output.
    dim3 qkv_grid(NQKV / 128, MROWS / 128);   // (48, 64)
    gemm_f16_kernel<true><<<qkv_grid, 256, GEMM_SMEM_BYTES>>>(
        xh, wqkvh, qkvh, MROWS, NQKV, D_DIM);

    // fp16 tensor-core causal flash attention.
    dim3 attn_grid(S_LEN / QT, NHEAD, B_SZ);  // (16, 16, 4)
    attn_f16_kernel<<<attn_grid, 256, ATT_SMEM_BYTES>>>(qkvh, oh);

    // Output projection: fp32 output.
    dim3 out_grid(D_DIM / 128, MROWS / 128);  // (16, 64)
    gemm_f16_kernel<false><<<out_grid, 256, GEMM_SMEM_BYTES>>>(
        oh, woh, out, MROWS, D_DIM, D_DIM);
}